// round 6
// baseline (speedup 1.0000x reference)
#include <cuda_runtime.h>
#include <cuda_bf16.h>
#include <cstdint>

// Problem constants (fixed by the reference)
#define NT      131072
#define HID     2048
#define NRANKS  8
#define NEXP    16
#define NSEG    128            // NRANKS * NEXP
#define VEC     (HID / 4)      // 512 float4 per row
#define TABN    (2 * NSEG + 1) // 129 out_off + 128 base_in

// Staging table in device memory (no allocation allowed):
//   [0 .. NSEG]          : exclusive cumsum of output-segment sizes (129)
//   [NSEG+1 .. 2*NSEG]   : input-row base per output segment (128)
__device__ int g_tab[TABN];
__constant__ int c_tab[TABN];

// -------------------------------------------------------------------------
// Setup: one block. Warp-shuffle scans over the 128 counts produce both
// tables; also writes the expert_token_num tail of the output.
// counts layout: counts[r * NEXP + e], rank-major (input order).
// Output segment order: p = e * NRANKS + r (expert-major, rank-minor).
// -------------------------------------------------------------------------
__global__ __launch_bounds__(128)
void moe_setup_kernel(const int* __restrict__ counts,
                      float* __restrict__ out,
                      long long out_elems) {
    __shared__ int sc[NSEG];
    __shared__ int s_in_off[NSEG];
    __shared__ int warp_sums[8];    // [0..3]: scan1, [4..7]: scan2

    const int tid = threadIdx.x;
    sc[tid] = counts[tid];
    __syncthreads();

    const int lane = tid & 31, w = tid >> 5;
    const int e = tid >> 3, r = tid & 7;

    // scan 1: input-order counts (for input offsets)
    int v1 = sc[tid], incl1 = v1;
    #pragma unroll
    for (int d = 1; d < 32; d <<= 1) {
        int y = __shfl_up_sync(0xffffffffu, incl1, d);
        if (lane >= d) incl1 += y;
    }
    // scan 2: output-order (permuted) counts
    int v2 = sc[r * NEXP + e], incl2 = v2;
    #pragma unroll
    for (int d = 1; d < 32; d <<= 1) {
        int y = __shfl_up_sync(0xffffffffu, incl2, d);
        if (lane >= d) incl2 += y;
    }
    if (lane == 31) { warp_sums[w] = incl1; warp_sums[4 + w] = incl2; }
    __syncthreads();

    int base1 = 0, base2 = 0;
    for (int i = 0; i < w; i++) { base1 += warp_sums[i]; base2 += warp_sums[4 + i]; }
    s_in_off[tid] = base1 + incl1 - v1;                 // exclusive, input order
    g_tab[tid]    = base2 + incl2 - v2;                 // exclusive, output order
    if (tid == NSEG - 1) g_tab[NSEG] = base2 + incl2;   // == NT
    __syncthreads();

    g_tab[NSEG + 1 + tid] = s_in_off[r * NEXP + e];     // base_in per out segment

    // expert_token_num tail
    if (tid < NEXP) {
        int s = 0;
        #pragma unroll
        for (int rr = 0; rr < NRANKS; rr++) s += sc[rr * NEXP + tid];
        long long pos = (long long)NT * HID + 2LL * NT + tid;
        if (pos < out_elems) out[pos] = (float)s;
    }
}

// -------------------------------------------------------------------------
// Gather: one block per output row, 128 threads x 4 float4 each (best
// measured shape — at the LTS ~6300 B/cyc chip cap). Source row resolved
// by a 7-step binary search in __constant__ memory (uniform LDC, ~30cyc
// per step). Lane 0 also emits the permuted scale and idx for this row.
// -------------------------------------------------------------------------
__global__ __launch_bounds__(128, 16)
void moe_gather_kernel(const float4* __restrict__ tokens,
                       const float* __restrict__ scales,
                       float* __restrict__ out) {
    const int row = blockIdx.x;

    int lo = 0, hi = NSEG - 1;
    #pragma unroll
    for (int it = 0; it < 7; it++) {
        int mid = (lo + hi + 1) >> 1;
        if (c_tab[mid] <= row) lo = mid; else hi = mid - 1;
    }
    const int src = c_tab[NSEG + 1 + lo] + (row - c_tab[lo]);

    const int t = threadIdx.x;
    const float4* __restrict__ in = tokens + (long long)src * VEC;
    float4* __restrict__ o = reinterpret_cast<float4*>(out) + (long long)row * VEC;

    float sc = 0.0f;
    if (t == 0) sc = scales[src];    // issue early; overlaps with row loads

    float4 a = __ldcs(in + t);
    float4 b = __ldcs(in + t + 128);
    float4 c = __ldcs(in + t + 256);
    float4 d = __ldcs(in + t + 384);
    __stcs(o + t,       a);
    __stcs(o + t + 128, b);
    __stcs(o + t + 256, c);
    __stcs(o + t + 384, d);

    if (t == 0) {
        const long long NH = (long long)NT * HID;
        out[NH + row]      = sc;
        out[NH + NT + row] = (float)src;   // idx < 2^24, exact in fp32
    }
}

extern "C" void kernel_launch(void* const* d_in, const int* in_sizes, int n_in,
                              void* d_out, int out_size) {
    const float* tokens = (const float*)d_in[0];
    const int*   counts = (const int*)d_in[1];   // [NRANKS, NEXP]
    const float* scales = (const float*)d_in[2];
    float* out = (float*)d_out;
    const long long out_elems = (long long)out_size;

    moe_setup_kernel<<<1, 128>>>(counts, out, out_elems);

    void* tab_dev = nullptr;
    cudaGetSymbolAddress(&tab_dev, g_tab);       // query only, no allocation
    cudaMemcpyToSymbolAsync(c_tab, tab_dev, TABN * sizeof(int), 0,
                            cudaMemcpyDeviceToDevice, 0);

    moe_gather_kernel<<<NT, 128>>>((const float4*)tokens, scales, out);
}

// round 7
// speedup vs baseline: 1.0209x; 1.0209x over previous
#include <cuda_runtime.h>
#include <cuda_bf16.h>
#include <cstdint>

// Problem constants (fixed by the reference)
#define NT      131072
#define HID     2048
#define NRANKS  8
#define NEXP    16
#define NSEG    128            // NRANKS * NEXP
#define VEC     (HID / 4)      // 512 float4 per row

// -------------------------------------------------------------------------
// Single fused kernel: one block per output row, 256 threads.
//
// Prologue (redundant per block, ~800 cyc, hidden by 8 blocks/SM):
//   threads 0..127 load the 128 counts (512 B, L2-resident after wave 1),
//   run two warp-shuffle scans (input-order and output-order cumsums),
//   and stage s_off[129] / s_base[128] in shared.
// Body: all 256 threads binary-search s_off (broadcast LDS, conflict-free)
//   for the uniform source row, then stream 2 float4 loads + 2 stores each.
// Tail: thread 0 emits permuted scale + idx; block 0 emits expert_token_num.
//
// counts layout: counts[r * NEXP + e], rank-major (input order).
// Output segment order: p = e * NRANKS + r (expert-major, rank-minor).
// -------------------------------------------------------------------------
__global__ __launch_bounds__(256, 8)
void moe_fused_kernel(const float4* __restrict__ tokens,
                      const int*    __restrict__ counts,
                      const float*  __restrict__ scales,
                      float*        __restrict__ out,
                      long long out_elems) {
    __shared__ int sc[NSEG];
    __shared__ int s_in_off[NSEG];
    __shared__ int s_off[NSEG + 1];
    __shared__ int s_base[NSEG];
    __shared__ int warp_sums[8];     // [0..3]: scan1, [4..7]: scan2

    const int tid = threadIdx.x;
    const int row = blockIdx.x;

    if (tid < NSEG) sc[tid] = __ldg(&counts[tid]);
    __syncthreads();

    if (tid < NSEG) {
        const int lane = tid & 31, w = tid >> 5;
        const int e = tid >> 3, r = tid & 7;

        // scan 1: input-order counts
        int v1 = sc[tid], incl1 = v1;
        #pragma unroll
        for (int d = 1; d < 32; d <<= 1) {
            int y = __shfl_up_sync(0xffffffffu, incl1, d);
            if (lane >= d) incl1 += y;
        }
        // scan 2: output-order (permuted) counts
        int v2 = sc[r * NEXP + e], incl2 = v2;
        #pragma unroll
        for (int d = 1; d < 32; d <<= 1) {
            int y = __shfl_up_sync(0xffffffffu, incl2, d);
            if (lane >= d) incl2 += y;
        }
        if (lane == 31) { warp_sums[w] = incl1; warp_sums[4 + w] = incl2; }
        __syncwarp();
        __syncthreads();

        int base1 = 0, base2 = 0;
        #pragma unroll
        for (int i = 0; i < 3; i++)
            if (i < w) { base1 += warp_sums[i]; base2 += warp_sums[4 + i]; }
        s_in_off[tid] = base1 + incl1 - v1;                 // exclusive
        s_off[tid]    = base2 + incl2 - v2;                 // exclusive
        if (tid == NSEG - 1) s_off[NSEG] = base2 + incl2;   // == NT
        __syncthreads();

        s_base[tid] = s_in_off[r * NEXP + e];
    } else {
        __syncthreads();
        __syncthreads();
    }
    __syncthreads();

    // uniform binary search (broadcast LDS -> conflict-free)
    int lo = 0, hi = NSEG - 1;
    #pragma unroll
    for (int it = 0; it < 7; it++) {
        int mid = (lo + hi + 1) >> 1;
        if (s_off[mid] <= row) lo = mid; else hi = mid - 1;
    }
    const int src = s_base[lo] + (row - s_off[lo]);

    const float4* __restrict__ in = tokens + (long long)src * VEC;
    float4* __restrict__ o = reinterpret_cast<float4*>(out) + (long long)row * VEC;

    float scv = 0.0f;
    if (tid == 0) scv = scales[src];     // overlaps with row loads

    float4 a = __ldcs(in + tid);
    float4 b = __ldcs(in + tid + 256);
    __stcs(o + tid,       a);
    __stcs(o + tid + 256, b);

    const long long NH = (long long)NT * HID;
    if (tid == 0) {
        out[NH + row]      = scv;
        out[NH + NT + row] = (float)src;  // idx < 2^24, exact in fp32
    }

    // expert_token_num tail (block 0 only)
    if (row == 0 && tid < NEXP) {
        int s = 0;
        #pragma unroll
        for (int rr = 0; rr < NRANKS; rr++) s += sc[rr * NEXP + tid];
        long long pos = NH + 2LL * NT + tid;
        if (pos < out_elems) out[pos] = (float)s;
    }
}

extern "C" void kernel_launch(void* const* d_in, const int* in_sizes, int n_in,
                              void* d_out, int out_size) {
    const float* tokens = (const float*)d_in[0];
    const int*   counts = (const int*)d_in[1];   // [NRANKS, NEXP]
    const float* scales = (const float*)d_in[2];
    float* out = (float*)d_out;

    moe_fused_kernel<<<NT, 256>>>((const float4*)tokens, counts, scales, out,
                                  (long long)out_size);
}